// round 9
// baseline (speedup 1.0000x reference)
#include <cuda_runtime.h>

// Problem constants (from reference: B=16, L=192, E=128, T=25)
#define BB    16
#define LL    192
#define EE    128
#define TT    25
#define NI    (LL - TT - 1)          // 166 block rows per batch (even)
#define LOUT  (TT + 1 + NI * LL)     // 31898 output rows per batch
#define E2    (EE / 2)               // 64 float2 per row
#define G     2                      // i-values per CTA (166 % 2 == 0)
#define NZ    8                      // l-slices per batch
#define LCH   (LL / NZ)              // 24 l-values per slice
#define NPREP (BB * NZ)              // 128 producer slices
#define NTIL  (NI / G)               // 83 i-tiles
#define TOTAL (NPREP * NTIL)         // 10624 CTAs

// s0 table: sigmoid(x*(W0-W1)+(b0-b1)). 1.5 MB, L2-resident.
__device__ __align__(16) float g_S[BB * LL * EE];
__device__ volatile int g_flag[NPREP];   // per-slice ready flags (reset at exit)
__device__ int g_exit;                   // exit ticket counter (reset at exit)

// Single fused kernel.
// Grid (128, 83): x = slice (b*8+zl)  [FASTEST-VARYING -> producer CTAs are
// bids 0..127, resident in wave 1], y = i-tile. 256 threads.
// tile==0 CTAs: produce S slice (b,zl) + head-copy rows, set flag, then do
// their own blocks work (no spin). tile>0 CTAs: load xi/xp, spin on slice
// flag, then stream. All sync state self-resets via an exit ticket.
__global__ void __launch_bounds__(256, 6)
fused_kernel(const float* __restrict__ x,
             const float* __restrict__ W,
             const float* __restrict__ bvec,
             float* __restrict__ out) {
    const int sl   = blockIdx.x;     // 0..127
    const int tile = blockIdx.y;     // 0..82
    const int b    = sl >> 3;
    const int zl   = sl & 7;
    const int tid  = threadIdx.x;
    const int lsub = tid >> 6;       // 0..3
    const int e2   = tid & 63;       // 0..63
    const int lbeg = zl * LCH;

    const float2* __restrict__ x2 = reinterpret_cast<const float2*>(x);
    float2* __restrict__ S2 = reinterpret_cast<float2*>(g_S);
    float2* __restrict__ o2 = reinterpret_cast<float2*>(out);

    const int i0 = tile * G;
    const int i1 = i0 + 1;

    // Prologue: xi/xp state (independent of S -> overlaps producer work).
    float2 a0 = __ldg(&x2[((size_t)b * LL + (TT + 1 + i0)) * E2 + e2]);
    float2 p0 = __ldg(&x2[((size_t)b * LL + (i0 + 1)) * E2 + e2]);
    float2 a1 = __ldg(&x2[((size_t)b * LL + (TT + 1 + i1)) * E2 + e2]);
    float2 p1 = __ldg(&x2[((size_t)b * LL + (i1 + 1)) * E2 + e2]);
    float2 d0 = make_float2(a0.x - p0.x, a0.y - p0.y);
    float2 d1 = make_float2(a1.x - p1.x, a1.y - p1.y);

    if (tile == 0) {
        // ---- Producer: compute S slice (b, lbeg..lbeg+23) ----
        const float dw = W[0] - W[1];
        const float db = bvec[0] - bvec[1];
#pragma unroll
        for (int k = 0; k < LCH / 4; k++) {
            int l = lbeg + lsub + 4 * k;
            float2 v = __ldg(&x2[((size_t)b * LL + l) * E2 + e2]);
            float2 s;
            s.x = __frcp_rn(1.0f + __expf(-fmaf(v.x, dw, db)));
            s.y = __frcp_rn(1.0f + __expf(-fmaf(v.y, dw, db)));
            S2[((size_t)b * LL + l) * E2 + e2] = s;
        }
        // Head copy: rows t = zl + 8*lsub (covers 0..25 exactly once over all slices)
        {
            int t = zl + 8 * lsub;
            if (t <= TT) {
                float2 v = __ldg(&x2[((size_t)b * LL + t) * E2 + e2]);
                o2[((size_t)b * LOUT + t) * E2 + e2] = v;
            }
        }
        __threadfence();            // publish S slice
        __syncthreads();
        if (tid == 0) g_flag[sl] = 1;
        __syncthreads();            // own slice visible to own threads
    } else {
        // ---- Consumer: wait for slice (b,zl) ----
        if (tid == 0) {
            while (g_flag[sl] == 0) { __nanosleep(64); }
        }
        __syncthreads();
        __threadfence();            // acquire before reading S
    }

    // ---- Stream: out[b, 26 + i*192 + l, :] = fma(d, s, p) ----
    const size_t outrow0 = (size_t)b * LOUT + (TT + 1);
    const float2* __restrict__ sp = S2 + ((size_t)b * LL + lbeg + lsub) * E2 + e2;
    float2* __restrict__ q0 = o2 + (outrow0 + (size_t)i0 * LL + lbeg + lsub) * E2 + e2;
    float2* __restrict__ q1 = o2 + (outrow0 + (size_t)i1 * LL + lbeg + lsub) * E2 + e2;

#pragma unroll
    for (int it = 0; it < LCH / 4; it++) {
        float2 s = __ldg(sp);
        float2 o0, o1;
        o0.x = fmaf(d0.x, s.x, p0.x);
        o0.y = fmaf(d0.y, s.y, p0.y);
        o1.x = fmaf(d1.x, s.x, p1.x);
        o1.y = fmaf(d1.y, s.y, p1.y);
        __stcs(q0, o0);
        __stcs(q1, o1);
        sp += 4 * E2;
        q0 += 4 * E2;
        q1 += 4 * E2;
    }

    // ---- Exit ticket: last CTA resets sync state for the next replay ----
    if (tid == 0) {
        int t = atomicAdd(&g_exit, 1);
        if (t == TOTAL - 1) {
            g_exit = 0;
#pragma unroll
            for (int i = 0; i < NPREP; i++) g_flag[i] = 0;
        }
    }
}

extern "C" void kernel_launch(void* const* d_in, const int* in_sizes, int n_in,
                              void* d_out, int out_size) {
    const float* x  = (const float*)d_in[0];
    const float* W  = (const float*)d_in[1];
    const float* bv = (const float*)d_in[2];
    float* out = (float*)d_out;

    dim3 grid(NPREP, NTIL);   // (128, 83) = 10624 CTAs; producers are bids 0..127
    fused_kernel<<<grid, 256>>>(x, W, bv, out);
}

// round 10
// speedup vs baseline: 1.1982x; 1.1982x over previous
#include <cuda_runtime.h>

// Problem constants (from reference: B=16, L=192, E=128, T=25)
#define BB   16
#define LL   192
#define EE   128
#define TT   25
#define NI   (LL - TT - 1)          // 166 block rows per batch (even)
#define LOUT (TT + 1 + NI * LL)     // 31898 output rows per batch
#define E2   (EE / 2)               // 64 float2 per row
#define E4   (EE / 4)               // 32 float4 per row
#define G    2                      // i-values per CTA
#define NZ   8                      // l-slices per (tile,b)
#define LCH  (LL / NZ)              // 24 l-values per slice

// s0 table: sigmoid(x*(W0-W1)+(b0-b1)). 1.5 MB, L2-resident.
__device__ __align__(16) float g_S[BB * LL * EE];

__device__ __forceinline__ float sigmoidf_fast(float z) {
    return __frcp_rn(1.0f + __expf(-z));
}

// Kernel 1 (producer): S table (float4-vectorized) + head copy.
// Triggers the dependent launch as soon as the S writes are fenced;
// the head-copy tail overlaps with the consumer's spin-up.
__global__ void __launch_bounds__(256)
prep_kernel(const float* __restrict__ x,
            const float* __restrict__ W,
            const float* __restrict__ bvec,
            float* __restrict__ out) {
    const int idx = blockIdx.x * blockDim.x + threadIdx.x;   // 0..98303
    const float dw = W[0] - W[1];
    const float db = bvec[0] - bvec[1];

    const float4* __restrict__ x4 = reinterpret_cast<const float4*>(x);
    float4* __restrict__ S4 = reinterpret_cast<float4*>(g_S);

    // S table: one float4 per thread (grid exactly covers 98304 float4s).
    float4 v = __ldg(&x4[idx]);
    float4 s;
    s.x = sigmoidf_fast(fmaf(v.x, dw, db));
    s.y = sigmoidf_fast(fmaf(v.y, dw, db));
    s.z = sigmoidf_fast(fmaf(v.z, dw, db));
    s.w = sigmoidf_fast(fmaf(v.w, dw, db));
    S4[idx] = s;

    __threadfence();
    cudaTriggerProgrammaticLaunchCompletion();

    // Head copy: out[:, :26, :] = x[:, :26, :]  (16*26*32 = 13312 float4s)
    if (idx < BB * (TT + 1) * E4) {
        int e = idx % E4;
        int t = (idx / E4) % (TT + 1);
        int b = idx / (E4 * (TT + 1));
        float4 h = __ldg(&x4[((size_t)b * LL + t) * E4 + e]);
        reinterpret_cast<float4*>(out)[((size_t)b * LOUT + t) * E4 + e] = h;
    }
}

// Kernel 2 (consumer): blocks[b,i,l,:] = fma(xi - xp, s0[b,l,:], xp)
// Grid (83,16,8) = 10624 CTAs, 256 threads. xi/xp prologue reads only x, so
// it runs during the PDL overlap window; grid-dependency sync before g_S.
// Inner body: 1 LDG.64 + 4 FMA + 2 STG.64 streaming (timed-best R4/R8 shape).
__global__ void __launch_bounds__(256, 8)
blocks_kernel(const float* __restrict__ x, float* __restrict__ out) {
    const int b    = blockIdx.y;
    const int tile = blockIdx.x;
    const int zl   = blockIdx.z;
    const int tid  = threadIdx.x;
    const int lsub = tid >> 6;       // 0..3
    const int e2   = tid & 63;       // 0..63

    const float2* __restrict__ x2 = reinterpret_cast<const float2*>(x);

    const int i0 = tile * G;
    const int i1 = i0 + 1;

    // Prologue (independent of g_S) — overlaps with prep via PDL.
    float2 a0 = __ldg(&x2[((size_t)b * LL + (TT + 1 + i0)) * E2 + e2]);
    float2 p0 = __ldg(&x2[((size_t)b * LL + (i0 + 1)) * E2 + e2]);
    float2 a1 = __ldg(&x2[((size_t)b * LL + (TT + 1 + i1)) * E2 + e2]);
    float2 p1 = __ldg(&x2[((size_t)b * LL + (i1 + 1)) * E2 + e2]);
    float2 d0 = make_float2(a0.x - p0.x, a0.y - p0.y);
    float2 d1 = make_float2(a1.x - p1.x, a1.y - p1.y);

    // Wait for prep's triggered completion (S table visible after this).
    cudaGridDependencySynchronize();

    const int lbeg = zl * LCH;
    const size_t outrow0 = (size_t)b * LOUT + (TT + 1);

    const float2* __restrict__ sp =
        reinterpret_cast<const float2*>(g_S) +
        ((size_t)b * LL + lbeg + lsub) * E2 + e2;
    float2* __restrict__ q0 =
        reinterpret_cast<float2*>(out) +
        (outrow0 + (size_t)i0 * LL + lbeg + lsub) * E2 + e2;
    float2* __restrict__ q1 =
        reinterpret_cast<float2*>(out) +
        (outrow0 + (size_t)i1 * LL + lbeg + lsub) * E2 + e2;

#pragma unroll
    for (int it = 0; it < LCH / 4; it++) {
        float2 s = __ldg(sp);
        float2 o0, o1;
        o0.x = fmaf(d0.x, s.x, p0.x);
        o0.y = fmaf(d0.y, s.y, p0.y);
        o1.x = fmaf(d1.x, s.x, p1.x);
        o1.y = fmaf(d1.y, s.y, p1.y);
        __stcs(q0, o0);
        __stcs(q1, o1);
        sp += 4 * E2;
        q0 += 4 * E2;
        q1 += 4 * E2;
    }
}

extern "C" void kernel_launch(void* const* d_in, const int* in_sizes, int n_in,
                              void* d_out, int out_size) {
    const float* x  = (const float*)d_in[0];
    const float* W  = (const float*)d_in[1];
    const float* bv = (const float*)d_in[2];
    float* out = (float*)d_out;

    // Producer: 98304 float4s -> 384 blocks of 256.
    prep_kernel<<<(BB * LL * E4 + 255) / 256, 256>>>(x, W, bv, out);

    // Consumer with programmatic dependent launch (overlaps its prologue
    // with the producer's tail).
    cudaLaunchAttribute attr[1];
    attr[0].id = cudaLaunchAttributeProgrammaticStreamSerialization;
    attr[0].val.programmaticStreamSerializationAllowed = 1;

    cudaLaunchConfig_t cfg = {};
    cfg.gridDim  = dim3(NI / G, BB, NZ);   // (83, 16, 8) = 10624 CTAs
    cfg.blockDim = dim3(256, 1, 1);
    cfg.dynamicSmemBytes = 0;
    cfg.stream = 0;                        // same (legacy default) stream as <<<>>>
    cfg.attrs = attr;
    cfg.numAttrs = 1;

    cudaLaunchKernelEx(&cfg, blocks_kernel, x, out);
}